// round 1
// baseline (speedup 1.0000x reference)
#include <cuda_runtime.h>

#define N_NODES 100000
#define E_EDGES 1600000
#define IN_C    32
#define HID     32
#define OUT_C   8
#define EDGE_D  16
#define GRAPH_D 16

// ---------------- device scratch (no allocations allowed) ----------------
__device__ float g_hi [N_NODES * HID];      // h_i = x@W_node + b
__device__ float g_Pr [N_NODES * EDGE_D];   // h_i @ W_edge_agg[0:32]
__device__ float g_Pc [N_NODES * EDGE_D];   // h_i @ W_edge_agg[32:64]
__device__ float g_mN [N_NODES * EDGE_D];   // scatter-sum of relu edge agg by row
__device__ float g_rcnt[N_NODES];           // count of edges per row
__device__ float g_ccnt[N_NODES];           // count of edges per col
__device__ float g_q  [N_NODES * OUT_C];    // h_i2 @ W_sage_l   (gathered in pass 2)
__device__ float g_s  [N_NODES * OUT_C];    // h_i2 @ W_sage_r
__device__ float g_aggq[N_NODES * OUT_C];   // scatter-sum of q[row] by col
__device__ float g_hG [GRAPH_D];            // graph embedding
__device__ float g_pool[OUT_C];             // global pool accumulator

// ---------------- kernel 0: zero the accumulators ----------------
__global__ void k_zero() {
    int i = blockIdx.x * blockDim.x + threadIdx.x;
    int stride = gridDim.x * blockDim.x;
    for (int t = i; t < N_NODES * EDGE_D; t += stride) g_mN[t] = 0.f;
    for (int t = i; t < N_NODES * OUT_C;  t += stride) g_aggq[t] = 0.f;
    for (int t = i; t < N_NODES;          t += stride) { g_rcnt[t] = 0.f; g_ccnt[t] = 0.f; }
    if (i < OUT_C) g_pool[i] = 0.f;
}

// ---------------- kernel 1: graph embedding (tiny) ----------------
__global__ void k_hG(const float* __restrict__ ga, const float* __restrict__ Wg,
                     const float* __restrict__ bg) {
    int j = threadIdx.x;
    if (j < GRAPH_D) {
        float acc = bg[j];
        #pragma unroll
        for (int k = 0; k < GRAPH_D; k++) acc += ga[k] * Wg[k * GRAPH_D + j];
        g_hG[j] = acc;
    }
}

// ---------------- kernel 2: per-node h_i, P_r, P_c ----------------
__global__ void k_nodeP(const float* __restrict__ x,
                        const float* __restrict__ Wn, const float* __restrict__ bn,
                        const float* __restrict__ Wea) {
    __shared__ float Wns[IN_C * HID];       // 32x32
    __shared__ float Weas[64 * EDGE_D];     // rows 0..63 of W_edge_agg
    __shared__ float bns[HID];
    for (int t = threadIdx.x; t < IN_C * HID; t += blockDim.x) Wns[t] = Wn[t];
    for (int t = threadIdx.x; t < 64 * EDGE_D; t += blockDim.x) Weas[t] = Wea[t];
    if (threadIdx.x < HID) bns[threadIdx.x] = bn[threadIdx.x];
    __syncthreads();

    int n = blockIdx.x * blockDim.x + threadIdx.x;
    if (n >= N_NODES) return;

    float acc[HID];
    #pragma unroll
    for (int j = 0; j < HID; j++) acc[j] = bns[j];
    const float4* xr = reinterpret_cast<const float4*>(x + (size_t)n * IN_C);
    #pragma unroll
    for (int k4 = 0; k4 < IN_C / 4; k4++) {
        float4 v = xr[k4];
        float vv[4] = {v.x, v.y, v.z, v.w};
        #pragma unroll
        for (int t = 0; t < 4; t++) {
            float xv = vv[t];
            int k = k4 * 4 + t;
            #pragma unroll
            for (int j = 0; j < HID; j++) acc[j] += xv * Wns[k * HID + j];
        }
    }
    // store h_i
    float4* ho = reinterpret_cast<float4*>(g_hi + (size_t)n * HID);
    #pragma unroll
    for (int j4 = 0; j4 < HID / 4; j4++)
        ho[j4] = make_float4(acc[j4*4], acc[j4*4+1], acc[j4*4+2], acc[j4*4+3]);

    // P_r / P_c projections
    float pr[EDGE_D], pc[EDGE_D];
    #pragma unroll
    for (int j = 0; j < EDGE_D; j++) { pr[j] = 0.f; pc[j] = 0.f; }
    #pragma unroll
    for (int k = 0; k < HID; k++) {
        float v = acc[k];
        #pragma unroll
        for (int j = 0; j < EDGE_D; j++) {
            pr[j] += v * Weas[k * EDGE_D + j];
            pc[j] += v * Weas[(32 + k) * EDGE_D + j];
        }
    }
    float4* po = reinterpret_cast<float4*>(g_Pr + (size_t)n * EDGE_D);
    float4* qo = reinterpret_cast<float4*>(g_Pc + (size_t)n * EDGE_D);
    #pragma unroll
    for (int j4 = 0; j4 < EDGE_D / 4; j4++) {
        po[j4] = make_float4(pr[j4*4], pr[j4*4+1], pr[j4*4+2], pr[j4*4+3]);
        qo[j4] = make_float4(pc[j4*4], pc[j4*4+1], pc[j4*4+2], pc[j4*4+3]);
    }
}

// ---------------- kernel 3: edge pass 1 (edge aggregator + scatter) ----------------
__global__ void k_edge1(const int* __restrict__ ei,
                        const float* __restrict__ edge_attr,
                        const float* __restrict__ Wea, const float* __restrict__ bea) {
    __shared__ float Wc[EDGE_D * EDGE_D];   // rows 64..79 (edge_attr part)
    __shared__ float base_s[EDGE_D];        // b + hG @ rows 80..95
    __shared__ float hGs[GRAPH_D];
    for (int t = threadIdx.x; t < EDGE_D * EDGE_D; t += blockDim.x)
        Wc[t] = Wea[64 * EDGE_D + t];
    if (threadIdx.x < GRAPH_D) hGs[threadIdx.x] = g_hG[threadIdx.x];
    __syncthreads();
    if (threadIdx.x < EDGE_D) {
        float b = bea[threadIdx.x];
        #pragma unroll
        for (int k = 0; k < GRAPH_D; k++)
            b += hGs[k] * Wea[(80 + k) * EDGE_D + threadIdx.x];
        base_s[threadIdx.x] = b;
    }
    __syncthreads();

    int e = blockIdx.x * blockDim.x + threadIdx.x;
    if (e >= E_EDGES) return;

    int row = ei[e];
    int col = ei[E_EDGES + e];

    float acc[EDGE_D];
    const float4* prp = reinterpret_cast<const float4*>(g_Pr + (size_t)row * EDGE_D);
    const float4* pcp = reinterpret_cast<const float4*>(g_Pc + (size_t)col * EDGE_D);
    #pragma unroll
    for (int j4 = 0; j4 < EDGE_D / 4; j4++) {
        float4 a = prp[j4];
        float4 b = pcp[j4];
        acc[j4*4+0] = base_s[j4*4+0] + a.x + b.x;
        acc[j4*4+1] = base_s[j4*4+1] + a.y + b.y;
        acc[j4*4+2] = base_s[j4*4+2] + a.z + b.z;
        acc[j4*4+3] = base_s[j4*4+3] + a.w + b.w;
    }
    const float4* eap = reinterpret_cast<const float4*>(edge_attr + (size_t)e * EDGE_D);
    #pragma unroll
    for (int k4 = 0; k4 < EDGE_D / 4; k4++) {
        float4 v = eap[k4];
        float vv[4] = {v.x, v.y, v.z, v.w};
        #pragma unroll
        for (int t = 0; t < 4; t++) {
            float ev = vv[t];
            int k = k4 * 4 + t;
            #pragma unroll
            for (int j = 0; j < EDGE_D; j++) acc[j] += ev * Wc[k * EDGE_D + j];
        }
    }
    float* mbase = g_mN + (size_t)row * EDGE_D;
    #pragma unroll
    for (int j = 0; j < EDGE_D; j++) {
        float v = fmaxf(acc[j], 0.f);
        atomicAdd(mbase + j, v);
    }
    atomicAdd(&g_rcnt[row], 1.f);
    atomicAdd(&g_ccnt[col], 1.f);
}

// ---------------- kernel 4: node aggregator + SAGE projections ----------------
__global__ void k_node2(const float* __restrict__ Wna, const float* __restrict__ bna,
                        const float* __restrict__ Wl,  const float* __restrict__ Wr) {
    __shared__ float Wnas[48 * HID];    // rows 0..47 (h_i and m_N parts)
    __shared__ float base_s[HID];       // b + hG @ rows 48..63
    __shared__ float Wls[HID * OUT_C];
    __shared__ float Wrs[HID * OUT_C];
    __shared__ float hGs[GRAPH_D];
    for (int t = threadIdx.x; t < 48 * HID; t += blockDim.x) Wnas[t] = Wna[t];
    for (int t = threadIdx.x; t < HID * OUT_C; t += blockDim.x) {
        Wls[t] = Wl[t]; Wrs[t] = Wr[t];
    }
    if (threadIdx.x < GRAPH_D) hGs[threadIdx.x] = g_hG[threadIdx.x];
    __syncthreads();
    if (threadIdx.x < HID) {
        float b = bna[threadIdx.x];
        #pragma unroll
        for (int k = 0; k < GRAPH_D; k++)
            b += hGs[k] * Wna[(48 + k) * HID + threadIdx.x];
        base_s[threadIdx.x] = b;
    }
    __syncthreads();

    int n = blockIdx.x * blockDim.x + threadIdx.x;
    if (n >= N_NODES) return;

    float acc[HID];
    #pragma unroll
    for (int j = 0; j < HID; j++) acc[j] = base_s[j];

    const float4* hr = reinterpret_cast<const float4*>(g_hi + (size_t)n * HID);
    #pragma unroll
    for (int k4 = 0; k4 < HID / 4; k4++) {
        float4 v = hr[k4];
        float vv[4] = {v.x, v.y, v.z, v.w};
        #pragma unroll
        for (int t = 0; t < 4; t++) {
            float hv = vv[t];
            int k = k4 * 4 + t;
            #pragma unroll
            for (int j = 0; j < HID; j++) acc[j] += hv * Wnas[k * HID + j];
        }
    }
    float inv_c = 1.f / fmaxf(g_rcnt[n], 1.f);
    const float4* mp = reinterpret_cast<const float4*>(g_mN + (size_t)n * EDGE_D);
    #pragma unroll
    for (int k4 = 0; k4 < EDGE_D / 4; k4++) {
        float4 v = mp[k4];
        float vv[4] = {v.x, v.y, v.z, v.w};
        #pragma unroll
        for (int t = 0; t < 4; t++) {
            float mv = vv[t] * inv_c;
            int k = 32 + k4 * 4 + t;
            #pragma unroll
            for (int j = 0; j < HID; j++) acc[j] += mv * Wnas[k * HID + j];
        }
    }
    #pragma unroll
    for (int j = 0; j < HID; j++) acc[j] = fmaxf(acc[j], 0.f);   // h_i2

    float q[OUT_C], s[OUT_C];
    #pragma unroll
    for (int j = 0; j < OUT_C; j++) { q[j] = 0.f; s[j] = 0.f; }
    #pragma unroll
    for (int k = 0; k < HID; k++) {
        float v = acc[k];
        #pragma unroll
        for (int j = 0; j < OUT_C; j++) {
            q[j] += v * Wls[k * OUT_C + j];
            s[j] += v * Wrs[k * OUT_C + j];
        }
    }
    float4* qo = reinterpret_cast<float4*>(g_q + (size_t)n * OUT_C);
    float4* so = reinterpret_cast<float4*>(g_s + (size_t)n * OUT_C);
    qo[0] = make_float4(q[0], q[1], q[2], q[3]);
    qo[1] = make_float4(q[4], q[5], q[6], q[7]);
    so[0] = make_float4(s[0], s[1], s[2], s[3]);
    so[1] = make_float4(s[4], s[5], s[6], s[7]);
}

// ---------------- kernel 5: edge pass 2 (SAGE gather/scatter of q) ----------------
__global__ void k_edge2(const int* __restrict__ ei) {
    int e = blockIdx.x * blockDim.x + threadIdx.x;
    if (e >= E_EDGES) return;
    int row = ei[e];
    int col = ei[E_EDGES + e];
    const float4* qp = reinterpret_cast<const float4*>(g_q + (size_t)row * OUT_C);
    float4 q0 = qp[0];
    float4 q1 = qp[1];
    float* ab = g_aggq + (size_t)col * OUT_C;
    atomicAdd(ab + 0, q0.x); atomicAdd(ab + 1, q0.y);
    atomicAdd(ab + 2, q0.z); atomicAdd(ab + 3, q0.w);
    atomicAdd(ab + 4, q1.x); atomicAdd(ab + 5, q1.y);
    atomicAdd(ab + 6, q1.z); atomicAdd(ab + 7, q1.w);
}

// ---------------- kernel 6: final node output + global mean pool ----------------
__global__ void k_node3(const float* __restrict__ bl) {
    __shared__ float pool_s[OUT_C];
    __shared__ float bls[OUT_C];
    if (threadIdx.x < OUT_C) { pool_s[threadIdx.x] = 0.f; bls[threadIdx.x] = bl[threadIdx.x]; }
    __syncthreads();

    int n = blockIdx.x * blockDim.x + threadIdx.x;
    if (n < N_NODES) {
        float inv_c = 1.f / fmaxf(g_ccnt[n], 1.f);
        const float4* ap = reinterpret_cast<const float4*>(g_aggq + (size_t)n * OUT_C);
        const float4* sp = reinterpret_cast<const float4*>(g_s + (size_t)n * OUT_C);
        float4 a0 = ap[0], a1 = ap[1], s0 = sp[0], s1 = sp[1];
        float hn[OUT_C];
        hn[0] = a0.x * inv_c + bls[0] + s0.x;
        hn[1] = a0.y * inv_c + bls[1] + s0.y;
        hn[2] = a0.z * inv_c + bls[2] + s0.z;
        hn[3] = a0.w * inv_c + bls[3] + s0.w;
        hn[4] = a1.x * inv_c + bls[4] + s1.x;
        hn[5] = a1.y * inv_c + bls[5] + s1.y;
        hn[6] = a1.z * inv_c + bls[6] + s1.z;
        hn[7] = a1.w * inv_c + bls[7] + s1.w;
        #pragma unroll
        for (int j = 0; j < OUT_C; j++) atomicAdd(&pool_s[j], hn[j]);
    }
    __syncthreads();
    if (threadIdx.x < OUT_C) atomicAdd(&g_pool[threadIdx.x], pool_s[threadIdx.x]);
}

// ---------------- kernel 7: pooled mean + log_softmax ----------------
__global__ void k_final(float* __restrict__ out) {
    if (threadIdx.x == 0) {
        float p[OUT_C];
        float mx = -1e30f;
        #pragma unroll
        for (int j = 0; j < OUT_C; j++) {
            p[j] = g_pool[j] / (float)N_NODES;
            mx = fmaxf(mx, p[j]);
        }
        float se = 0.f;
        #pragma unroll
        for (int j = 0; j < OUT_C; j++) se += expf(p[j] - mx);
        float lse = mx + logf(se);
        #pragma unroll
        for (int j = 0; j < OUT_C; j++) out[j] = p[j] - lse;
    }
}

// ---------------- launch ----------------
extern "C" void kernel_launch(void* const* d_in, const int* in_sizes, int n_in,
                              void* d_out, int out_size) {
    const float* x          = (const float*)d_in[0];
    const float* edge_attr  = (const float*)d_in[1];
    const float* graph_attr = (const float*)d_in[2];
    const int*   edge_index = (const int*)  d_in[3];
    // d_in[4] = batch (all zeros, count == N_NODES) — unused
    const float* W_node     = (const float*)d_in[5];
    const float* b_node     = (const float*)d_in[6];
    const float* W_graph    = (const float*)d_in[7];
    const float* b_graph    = (const float*)d_in[8];
    const float* W_edge_agg = (const float*)d_in[9];
    const float* b_edge_agg = (const float*)d_in[10];
    const float* W_node_agg = (const float*)d_in[11];
    const float* b_node_agg = (const float*)d_in[12];
    const float* W_sage_l   = (const float*)d_in[13];
    const float* b_sage_l   = (const float*)d_in[14];
    const float* W_sage_r   = (const float*)d_in[15];
    float* out = (float*)d_out;

    const int TB = 256;
    const int nodeBlocks = (N_NODES + TB - 1) / TB;
    const int edgeBlocks = (E_EDGES + TB - 1) / TB;

    k_zero<<<1024, 256>>>();
    k_hG<<<1, 32>>>(graph_attr, W_graph, b_graph);
    k_nodeP<<<nodeBlocks, TB>>>(x, W_node, b_node, W_edge_agg);
    k_edge1<<<edgeBlocks, TB>>>(edge_index, edge_attr, W_edge_agg, b_edge_agg);
    k_node2<<<nodeBlocks, TB>>>(W_node_agg, b_node_agg, W_sage_l, W_sage_r);
    k_edge2<<<edgeBlocks, TB>>>(edge_index);
    k_node3<<<nodeBlocks, TB>>>(b_sage_l);
    k_final<<<1, 32>>>(out);
}

// round 2
// speedup vs baseline: 1.7395x; 1.7395x over previous
#include <cuda_runtime.h>

#define N_NODES 100000
#define E_EDGES 1600000
#define IN_C    32
#define HID     32
#define OUT_C   8
#define EDGE_D  16
#define GRAPH_D 16

// ---------------- device scratch (no allocations allowed) ----------------
__device__ float g_hi [N_NODES * HID];      // h_i = x@W_node + b
__device__ float g_Pr [N_NODES * EDGE_D];   // h_i @ W_edge_agg[0:32]  (+ bias + hG term folded in)
__device__ float g_Pc [N_NODES * EDGE_D];   // h_i @ W_edge_agg[32:64]
__device__ float g_mN [N_NODES * EDGE_D];   // scatter-sum of relu edge agg by row
__device__ float g_rcnt[N_NODES];           // count of edges per row
__device__ float g_ccnt[N_NODES];           // count of edges per col
__device__ float g_q  [N_NODES * OUT_C];    // h_i2 @ W_sage_l   (gathered in pass 2)
__device__ float g_s  [N_NODES * OUT_C];    // h_i2 @ W_sage_r
__device__ float g_aggq[N_NODES * OUT_C];   // scatter-sum of q[row] by col
__device__ float g_hG [GRAPH_D];            // graph embedding
__device__ float g_pool[OUT_C];             // global pool accumulator

// vectorized L2 reduction: one LTS op per 16 bytes (sm_90+)
__device__ __forceinline__ void red_add_f4(float* addr, float a, float b, float c, float d) {
    asm volatile("red.global.add.v4.f32 [%0], {%1,%2,%3,%4};"
                 :: "l"(addr), "f"(a), "f"(b), "f"(c), "f"(d) : "memory");
}

// ---------------- kernel 0: zero the accumulators ----------------
__global__ void k_zero() {
    int i = blockIdx.x * blockDim.x + threadIdx.x;
    int stride = gridDim.x * blockDim.x;
    for (int t = i; t < N_NODES * EDGE_D; t += stride) g_mN[t] = 0.f;
    for (int t = i; t < N_NODES * OUT_C;  t += stride) g_aggq[t] = 0.f;
    for (int t = i; t < N_NODES;          t += stride) { g_rcnt[t] = 0.f; g_ccnt[t] = 0.f; }
    if (i < OUT_C) g_pool[i] = 0.f;
}

// ---------------- kernel 1: graph embedding (tiny) ----------------
__global__ void k_hG(const float* __restrict__ ga, const float* __restrict__ Wg,
                     const float* __restrict__ bg) {
    int j = threadIdx.x;
    if (j < GRAPH_D) {
        float acc = bg[j];
        #pragma unroll
        for (int k = 0; k < GRAPH_D; k++) acc += ga[k] * Wg[k * GRAPH_D + j];
        g_hG[j] = acc;
    }
}

// ---------------- kernel 2: per-node h_i, P_r (with base folded), P_c ----------------
__global__ void __launch_bounds__(256)
k_nodeP(const float* __restrict__ x,
        const float* __restrict__ Wn, const float* __restrict__ bn,
        const float* __restrict__ Wea, const float* __restrict__ bea) {
    __shared__ float Wns[IN_C * HID];       // 32x32
    __shared__ float Weas[64 * EDGE_D];     // rows 0..63 of W_edge_agg
    __shared__ float bns[HID];
    __shared__ float base_s[EDGE_D];        // b_edge_agg + hG @ rows 80..95
    for (int t = threadIdx.x; t < IN_C * HID; t += blockDim.x) Wns[t] = Wn[t];
    for (int t = threadIdx.x; t < 64 * EDGE_D; t += blockDim.x) Weas[t] = Wea[t];
    if (threadIdx.x < HID) bns[threadIdx.x] = bn[threadIdx.x];
    if (threadIdx.x >= 32 && threadIdx.x < 32 + EDGE_D) {
        int j = threadIdx.x - 32;
        float b = bea[j];
        #pragma unroll
        for (int k = 0; k < GRAPH_D; k++)
            b += g_hG[k] * Wea[(80 + k) * EDGE_D + j];
        base_s[j] = b;
    }
    __syncthreads();

    int n = blockIdx.x * blockDim.x + threadIdx.x;
    if (n >= N_NODES) return;

    float acc[HID];
    #pragma unroll
    for (int j = 0; j < HID; j++) acc[j] = bns[j];
    const float4* xr = reinterpret_cast<const float4*>(x + (size_t)n * IN_C);
    #pragma unroll
    for (int k4 = 0; k4 < IN_C / 4; k4++) {
        float4 v = xr[k4];
        float vv[4] = {v.x, v.y, v.z, v.w};
        #pragma unroll
        for (int t = 0; t < 4; t++) {
            float xv = vv[t];
            int k = k4 * 4 + t;
            #pragma unroll
            for (int j = 0; j < HID; j++) acc[j] += xv * Wns[k * HID + j];
        }
    }
    // store h_i
    float4* ho = reinterpret_cast<float4*>(g_hi + (size_t)n * HID);
    #pragma unroll
    for (int j4 = 0; j4 < HID / 4; j4++)
        ho[j4] = make_float4(acc[j4*4], acc[j4*4+1], acc[j4*4+2], acc[j4*4+3]);

    // P_r / P_c projections; fold the constant (bias + hG) term into P_r
    float pr[EDGE_D], pc[EDGE_D];
    #pragma unroll
    for (int j = 0; j < EDGE_D; j++) { pr[j] = base_s[j]; pc[j] = 0.f; }
    #pragma unroll
    for (int k = 0; k < HID; k++) {
        float v = acc[k];
        #pragma unroll
        for (int j = 0; j < EDGE_D; j++) {
            pr[j] += v * Weas[k * EDGE_D + j];
            pc[j] += v * Weas[(32 + k) * EDGE_D + j];
        }
    }
    float4* po = reinterpret_cast<float4*>(g_Pr + (size_t)n * EDGE_D);
    float4* qo = reinterpret_cast<float4*>(g_Pc + (size_t)n * EDGE_D);
    #pragma unroll
    for (int j4 = 0; j4 < EDGE_D / 4; j4++) {
        po[j4] = make_float4(pr[j4*4], pr[j4*4+1], pr[j4*4+2], pr[j4*4+3]);
        qo[j4] = make_float4(pc[j4*4], pc[j4*4+1], pc[j4*4+2], pc[j4*4+3]);
    }
}

// ---------------- kernel 3: edge pass 1 (edge aggregator + vector scatter) ----------------
__global__ void __launch_bounds__(256)
k_edge1(const int* __restrict__ ei,
        const float* __restrict__ edge_attr,
        const float* __restrict__ Wea) {
    __shared__ float Wc[EDGE_D * EDGE_D];   // rows 64..79 (edge_attr part)
    for (int t = threadIdx.x; t < EDGE_D * EDGE_D; t += blockDim.x)
        Wc[t] = Wea[64 * EDGE_D + t];
    __syncthreads();

    int e = blockIdx.x * blockDim.x + threadIdx.x;
    if (e >= E_EDGES) return;

    int row = ei[e];
    int col = ei[E_EDGES + e];

    float acc[EDGE_D];
    const float4* prp = reinterpret_cast<const float4*>(g_Pr + (size_t)row * EDGE_D);
    const float4* pcp = reinterpret_cast<const float4*>(g_Pc + (size_t)col * EDGE_D);
    #pragma unroll
    for (int j4 = 0; j4 < EDGE_D / 4; j4++) {
        float4 a = prp[j4];
        float4 b = pcp[j4];
        acc[j4*4+0] = a.x + b.x;
        acc[j4*4+1] = a.y + b.y;
        acc[j4*4+2] = a.z + b.z;
        acc[j4*4+3] = a.w + b.w;
    }
    const float4* eap = reinterpret_cast<const float4*>(edge_attr + (size_t)e * EDGE_D);
    #pragma unroll
    for (int k4 = 0; k4 < EDGE_D / 4; k4++) {
        float4 v = eap[k4];
        float vv[4] = {v.x, v.y, v.z, v.w};
        #pragma unroll
        for (int t = 0; t < 4; t++) {
            float ev = vv[t];
            int k = k4 * 4 + t;
            #pragma unroll
            for (int j = 0; j < EDGE_D; j++) acc[j] += ev * Wc[k * EDGE_D + j];
        }
    }
    float* mbase = g_mN + (size_t)row * EDGE_D;
    #pragma unroll
    for (int j4 = 0; j4 < EDGE_D / 4; j4++) {
        red_add_f4(mbase + j4 * 4,
                   fmaxf(acc[j4*4+0], 0.f), fmaxf(acc[j4*4+1], 0.f),
                   fmaxf(acc[j4*4+2], 0.f), fmaxf(acc[j4*4+3], 0.f));
    }
    atomicAdd(&g_rcnt[row], 1.f);
}

// ---------------- kernel 4: node aggregator + SAGE projections ----------------
__global__ void __launch_bounds__(256)
k_node2(const float* __restrict__ Wna, const float* __restrict__ bna,
        const float* __restrict__ Wl,  const float* __restrict__ Wr) {
    __shared__ float Wnas[48 * HID];    // rows 0..47 (h_i and m_N parts)
    __shared__ float base_s[HID];       // b + hG @ rows 48..63
    __shared__ float Wls[HID * OUT_C];
    __shared__ float Wrs[HID * OUT_C];
    for (int t = threadIdx.x; t < 48 * HID; t += blockDim.x) Wnas[t] = Wna[t];
    for (int t = threadIdx.x; t < HID * OUT_C; t += blockDim.x) {
        Wls[t] = Wl[t]; Wrs[t] = Wr[t];
    }
    if (threadIdx.x < HID) {
        float b = bna[threadIdx.x];
        #pragma unroll
        for (int k = 0; k < GRAPH_D; k++)
            b += g_hG[k] * Wna[(48 + k) * HID + threadIdx.x];
        base_s[threadIdx.x] = b;
    }
    __syncthreads();

    int n = blockIdx.x * blockDim.x + threadIdx.x;
    if (n >= N_NODES) return;

    float acc[HID];
    #pragma unroll
    for (int j = 0; j < HID; j++) acc[j] = base_s[j];

    const float4* hr = reinterpret_cast<const float4*>(g_hi + (size_t)n * HID);
    #pragma unroll
    for (int k4 = 0; k4 < HID / 4; k4++) {
        float4 v = hr[k4];
        float vv[4] = {v.x, v.y, v.z, v.w};
        #pragma unroll
        for (int t = 0; t < 4; t++) {
            float hv = vv[t];
            int k = k4 * 4 + t;
            #pragma unroll
            for (int j = 0; j < HID; j++) acc[j] += hv * Wnas[k * HID + j];
        }
    }
    float inv_c = 1.f / fmaxf(g_rcnt[n], 1.f);
    const float4* mp = reinterpret_cast<const float4*>(g_mN + (size_t)n * EDGE_D);
    #pragma unroll
    for (int k4 = 0; k4 < EDGE_D / 4; k4++) {
        float4 v = mp[k4];
        float vv[4] = {v.x, v.y, v.z, v.w};
        #pragma unroll
        for (int t = 0; t < 4; t++) {
            float mv = vv[t] * inv_c;
            int k = 32 + k4 * 4 + t;
            #pragma unroll
            for (int j = 0; j < HID; j++) acc[j] += mv * Wnas[k * HID + j];
        }
    }
    #pragma unroll
    for (int j = 0; j < HID; j++) acc[j] = fmaxf(acc[j], 0.f);   // h_i2

    float q[OUT_C], s[OUT_C];
    #pragma unroll
    for (int j = 0; j < OUT_C; j++) { q[j] = 0.f; s[j] = 0.f; }
    #pragma unroll
    for (int k = 0; k < HID; k++) {
        float v = acc[k];
        #pragma unroll
        for (int j = 0; j < OUT_C; j++) {
            q[j] += v * Wls[k * OUT_C + j];
            s[j] += v * Wrs[k * OUT_C + j];
        }
    }
    float4* qo = reinterpret_cast<float4*>(g_q + (size_t)n * OUT_C);
    float4* so = reinterpret_cast<float4*>(g_s + (size_t)n * OUT_C);
    qo[0] = make_float4(q[0], q[1], q[2], q[3]);
    qo[1] = make_float4(q[4], q[5], q[6], q[7]);
    so[0] = make_float4(s[0], s[1], s[2], s[3]);
    so[1] = make_float4(s[4], s[5], s[6], s[7]);
}

// ---------------- kernel 5: edge pass 2 (SAGE gather/scatter of q, + ccnt) ----------------
__global__ void __launch_bounds__(256)
k_edge2(const int* __restrict__ ei) {
    int e = blockIdx.x * blockDim.x + threadIdx.x;
    if (e >= E_EDGES) return;
    int row = ei[e];
    int col = ei[E_EDGES + e];
    const float4* qp = reinterpret_cast<const float4*>(g_q + (size_t)row * OUT_C);
    float4 q0 = qp[0];
    float4 q1 = qp[1];
    float* ab = g_aggq + (size_t)col * OUT_C;
    red_add_f4(ab + 0, q0.x, q0.y, q0.z, q0.w);
    red_add_f4(ab + 4, q1.x, q1.y, q1.z, q1.w);
    atomicAdd(&g_ccnt[col], 1.f);
}

// ---------------- kernel 6: final node output + global mean pool ----------------
__global__ void __launch_bounds__(256)
k_node3(const float* __restrict__ bl) {
    __shared__ float pool_s[OUT_C];
    __shared__ float bls[OUT_C];
    if (threadIdx.x < OUT_C) { pool_s[threadIdx.x] = 0.f; bls[threadIdx.x] = bl[threadIdx.x]; }
    __syncthreads();

    int n = blockIdx.x * blockDim.x + threadIdx.x;
    float hn[OUT_C];
    #pragma unroll
    for (int j = 0; j < OUT_C; j++) hn[j] = 0.f;
    if (n < N_NODES) {
        float inv_c = 1.f / fmaxf(g_ccnt[n], 1.f);
        const float4* ap = reinterpret_cast<const float4*>(g_aggq + (size_t)n * OUT_C);
        const float4* sp = reinterpret_cast<const float4*>(g_s + (size_t)n * OUT_C);
        float4 a0 = ap[0], a1 = ap[1], s0 = sp[0], s1 = sp[1];
        hn[0] = a0.x * inv_c + bls[0] + s0.x;
        hn[1] = a0.y * inv_c + bls[1] + s0.y;
        hn[2] = a0.z * inv_c + bls[2] + s0.z;
        hn[3] = a0.w * inv_c + bls[3] + s0.w;
        hn[4] = a1.x * inv_c + bls[4] + s1.x;
        hn[5] = a1.y * inv_c + bls[5] + s1.y;
        hn[6] = a1.z * inv_c + bls[6] + s1.z;
        hn[7] = a1.w * inv_c + bls[7] + s1.w;
    }
    // warp-level reduction first, then one shared atomic per warp per component
    #pragma unroll
    for (int j = 0; j < OUT_C; j++) {
        float v = hn[j];
        #pragma unroll
        for (int off = 16; off > 0; off >>= 1)
            v += __shfl_down_sync(0xFFFFFFFFu, v, off);
        if ((threadIdx.x & 31) == 0) atomicAdd(&pool_s[j], v);
    }
    __syncthreads();
    if (threadIdx.x < OUT_C) atomicAdd(&g_pool[threadIdx.x], pool_s[threadIdx.x]);
}

// ---------------- kernel 7: pooled mean + log_softmax ----------------
__global__ void k_final(float* __restrict__ out) {
    if (threadIdx.x == 0) {
        float p[OUT_C];
        float mx = -1e30f;
        #pragma unroll
        for (int j = 0; j < OUT_C; j++) {
            p[j] = g_pool[j] / (float)N_NODES;
            mx = fmaxf(mx, p[j]);
        }
        float se = 0.f;
        #pragma unroll
        for (int j = 0; j < OUT_C; j++) se += expf(p[j] - mx);
        float lse = mx + logf(se);
        #pragma unroll
        for (int j = 0; j < OUT_C; j++) out[j] = p[j] - lse;
    }
}

// ---------------- launch ----------------
extern "C" void kernel_launch(void* const* d_in, const int* in_sizes, int n_in,
                              void* d_out, int out_size) {
    const float* x          = (const float*)d_in[0];
    const float* edge_attr  = (const float*)d_in[1];
    const float* graph_attr = (const float*)d_in[2];
    const int*   edge_index = (const int*)  d_in[3];
    // d_in[4] = batch (all zeros) — unused
    const float* W_node     = (const float*)d_in[5];
    const float* b_node     = (const float*)d_in[6];
    const float* W_graph    = (const float*)d_in[7];
    const float* b_graph    = (const float*)d_in[8];
    const float* W_edge_agg = (const float*)d_in[9];
    const float* b_edge_agg = (const float*)d_in[10];
    const float* W_node_agg = (const float*)d_in[11];
    const float* b_node_agg = (const float*)d_in[12];
    const float* W_sage_l   = (const float*)d_in[13];
    const float* b_sage_l   = (const float*)d_in[14];
    const float* W_sage_r   = (const float*)d_in[15];
    float* out = (float*)d_out;

    const int TB = 256;
    const int nodeBlocks = (N_NODES + TB - 1) / TB;
    const int edgeBlocks = (E_EDGES + TB - 1) / TB;

    k_zero<<<1024, 256>>>();
    k_hG<<<1, 32>>>(graph_attr, W_graph, b_graph);
    k_nodeP<<<nodeBlocks, TB>>>(x, W_node, b_node, W_edge_agg, b_edge_agg);
    k_edge1<<<edgeBlocks, TB>>>(edge_index, edge_attr, W_edge_agg);
    k_node2<<<nodeBlocks, TB>>>(W_node_agg, b_node_agg, W_sage_l, W_sage_r);
    k_edge2<<<edgeBlocks, TB>>>(edge_index);
    k_node3<<<nodeBlocks, TB>>>(b_sage_l);
    k_final<<<1, 32>>>(out);
}

// round 3
// speedup vs baseline: 1.8587x; 1.0685x over previous
#include <cuda_runtime.h>

#define N_NODES 100000
#define E_EDGES 1600000
#define IN_C    32
#define HID     32
#define OUT_C   8
#define EDGE_D  16
#define GRAPH_D 16

// ---------------- device scratch (no allocations allowed) ----------------
__device__ float g_hi [N_NODES * HID];      // h_i = x@W_node + b
__device__ float g_Pr [N_NODES * EDGE_D];   // h_i @ W_edge_agg[0:32]  (+ bias + hG folded in)
__device__ float g_Pc [N_NODES * EDGE_D];   // h_i @ W_edge_agg[32:64]
__device__ float g_mN [N_NODES * EDGE_D];   // scatter-sum of relu edge agg by row
__device__ float g_rcnt[N_NODES];           // edges per row
__device__ float g_ccnt[N_NODES];           // edges per col
__device__ float g_q  [N_NODES * OUT_C];    // h_i2 @ W_sage_l
__device__ float g_s  [N_NODES * OUT_C];    // h_i2 @ W_sage_r
__device__ float g_aggq[N_NODES * OUT_C];   // scatter-sum of q[row] by col
__device__ float g_hG [GRAPH_D];
__device__ float g_pool[OUT_C];

// vectorized L2 reduction: one LTS op per 16 bytes (sm_90+)
__device__ __forceinline__ void red_add_f4(float* addr, float a, float b, float c, float d) {
    asm volatile("red.global.add.v4.f32 [%0], {%1,%2,%3,%4};"
                 :: "l"(addr), "f"(a), "f"(b), "f"(c), "f"(d) : "memory");
}

// ---------------- kernel 1: graph embedding + pool zero (tiny) ----------------
__global__ void k_hG(const float* __restrict__ ga, const float* __restrict__ Wg,
                     const float* __restrict__ bg) {
    int j = threadIdx.x;
    if (j < GRAPH_D) {
        float acc = bg[j];
        #pragma unroll
        for (int k = 0; k < GRAPH_D; k++) acc += ga[k] * Wg[k * GRAPH_D + j];
        g_hG[j] = acc;
    }
    if (j < OUT_C) g_pool[j] = 0.f;
}

// ---------------- kernel 2: per-node h_i, P_r, P_c + zero accumulators ----------------
__global__ void __launch_bounds__(256)
k_nodeP(const float* __restrict__ x,
        const float* __restrict__ Wn, const float* __restrict__ bn,
        const float* __restrict__ Wea, const float* __restrict__ bea) {
    __shared__ float Wns[IN_C * HID];       // 32x32
    __shared__ float Weas[64 * EDGE_D];     // rows 0..63 of W_edge_agg
    __shared__ float bns[HID];
    __shared__ float base_s[EDGE_D];        // b_edge_agg + hG @ rows 80..95
    for (int t = threadIdx.x; t < IN_C * HID; t += blockDim.x) Wns[t] = Wn[t];
    for (int t = threadIdx.x; t < 64 * EDGE_D; t += blockDim.x) Weas[t] = Wea[t];
    if (threadIdx.x < HID) bns[threadIdx.x] = bn[threadIdx.x];
    if (threadIdx.x >= 32 && threadIdx.x < 32 + EDGE_D) {
        int j = threadIdx.x - 32;
        float b = bea[j];
        #pragma unroll
        for (int k = 0; k < GRAPH_D; k++)
            b += g_hG[k] * Wea[(80 + k) * EDGE_D + j];
        base_s[j] = b;
    }
    __syncthreads();

    int n = blockIdx.x * blockDim.x + threadIdx.x;
    if (n >= N_NODES) return;

    // zero the per-node accumulators (replaces k_zero pass)
    float4 z4 = make_float4(0.f, 0.f, 0.f, 0.f);
    float4* mz = reinterpret_cast<float4*>(g_mN + (size_t)n * EDGE_D);
    mz[0] = z4; mz[1] = z4; mz[2] = z4; mz[3] = z4;
    float4* az = reinterpret_cast<float4*>(g_aggq + (size_t)n * OUT_C);
    az[0] = z4; az[1] = z4;
    g_rcnt[n] = 0.f;
    g_ccnt[n] = 0.f;

    float acc[HID];
    #pragma unroll
    for (int j = 0; j < HID; j++) acc[j] = bns[j];
    const float4* xr = reinterpret_cast<const float4*>(x + (size_t)n * IN_C);
    #pragma unroll
    for (int k4 = 0; k4 < IN_C / 4; k4++) {
        float4 v = xr[k4];
        float vv[4] = {v.x, v.y, v.z, v.w};
        #pragma unroll
        for (int t = 0; t < 4; t++) {
            float xv = vv[t];
            int k = k4 * 4 + t;
            #pragma unroll
            for (int j = 0; j < HID; j++) acc[j] += xv * Wns[k * HID + j];
        }
    }
    float4* ho = reinterpret_cast<float4*>(g_hi + (size_t)n * HID);
    #pragma unroll
    for (int j4 = 0; j4 < HID / 4; j4++)
        ho[j4] = make_float4(acc[j4*4], acc[j4*4+1], acc[j4*4+2], acc[j4*4+3]);

    float pr[EDGE_D], pc[EDGE_D];
    #pragma unroll
    for (int j = 0; j < EDGE_D; j++) { pr[j] = base_s[j]; pc[j] = 0.f; }
    #pragma unroll
    for (int k = 0; k < HID; k++) {
        float v = acc[k];
        #pragma unroll
        for (int j = 0; j < EDGE_D; j++) {
            pr[j] += v * Weas[k * EDGE_D + j];
            pc[j] += v * Weas[(32 + k) * EDGE_D + j];
        }
    }
    float4* po = reinterpret_cast<float4*>(g_Pr + (size_t)n * EDGE_D);
    float4* qo = reinterpret_cast<float4*>(g_Pc + (size_t)n * EDGE_D);
    #pragma unroll
    for (int j4 = 0; j4 < EDGE_D / 4; j4++) {
        po[j4] = make_float4(pr[j4*4], pr[j4*4+1], pr[j4*4+2], pr[j4*4+3]);
        qo[j4] = make_float4(pc[j4*4], pc[j4*4+1], pc[j4*4+2], pc[j4*4+3]);
    }
}

// ---------------- kernel 3: edge pass 1 — 4 threads per edge ----------------
// Lane group of 4 handles one edge; thread c owns channels [4c, 4c+4).
// Gathers become one contiguous 64B row per edge (coalesced across the group).
__global__ void __launch_bounds__(256)
k_edge1(const int* __restrict__ ei,
        const float* __restrict__ edge_attr,
        const float* __restrict__ Wea) {
    __shared__ float Wc[EDGE_D * EDGE_D];   // rows 64..79 (edge_attr part)
    for (int t = threadIdx.x; t < EDGE_D * EDGE_D; t += blockDim.x)
        Wc[t] = Wea[64 * EDGE_D + t];
    __syncthreads();

    int t = blockIdx.x * blockDim.x + threadIdx.x;
    int e = t >> 2;
    if (e >= E_EDGES) return;
    int c = threadIdx.x & 3;

    int row = ei[e];
    int col = ei[E_EDGES + e];

    float4 pr = *reinterpret_cast<const float4*>(g_Pr + (size_t)row * EDGE_D + c * 4);
    float4 pc = *reinterpret_cast<const float4*>(g_Pc + (size_t)col * EDGE_D + c * 4);
    // fully coalesced: element index = 4 * t
    float4 ea = *reinterpret_cast<const float4*>(edge_attr + (size_t)e * EDGE_D + c * 4);

    float acc[4] = {pr.x + pc.x, pr.y + pc.y, pr.z + pc.z, pr.w + pc.w};

    #pragma unroll
    for (int src = 0; src < 4; src++) {
        float ev[4];
        ev[0] = __shfl_sync(0xFFFFFFFFu, ea.x, src, 4);
        ev[1] = __shfl_sync(0xFFFFFFFFu, ea.y, src, 4);
        ev[2] = __shfl_sync(0xFFFFFFFFu, ea.z, src, 4);
        ev[3] = __shfl_sync(0xFFFFFFFFu, ea.w, src, 4);
        #pragma unroll
        for (int kk = 0; kk < 4; kk++) {
            int k = src * 4 + kk;
            #pragma unroll
            for (int j = 0; j < 4; j++)
                acc[j] += ev[kk] * Wc[k * EDGE_D + c * 4 + j];
        }
    }
    red_add_f4(g_mN + (size_t)row * EDGE_D + c * 4,
               fmaxf(acc[0], 0.f), fmaxf(acc[1], 0.f),
               fmaxf(acc[2], 0.f), fmaxf(acc[3], 0.f));
    if (c == 0) atomicAdd(&g_rcnt[row], 1.f);
}

// ---------------- kernel 4: node aggregator + SAGE projections ----------------
__global__ void __launch_bounds__(256)
k_node2(const float* __restrict__ Wna, const float* __restrict__ bna,
        const float* __restrict__ Wl,  const float* __restrict__ Wr) {
    __shared__ float Wnas[48 * HID];    // rows 0..47 (h_i and m_N parts)
    __shared__ float base_s[HID];       // b + hG @ rows 48..63
    __shared__ float Wls[HID * OUT_C];
    __shared__ float Wrs[HID * OUT_C];
    for (int t = threadIdx.x; t < 48 * HID; t += blockDim.x) Wnas[t] = Wna[t];
    for (int t = threadIdx.x; t < HID * OUT_C; t += blockDim.x) {
        Wls[t] = Wl[t]; Wrs[t] = Wr[t];
    }
    if (threadIdx.x < HID) {
        float b = bna[threadIdx.x];
        #pragma unroll
        for (int k = 0; k < GRAPH_D; k++)
            b += g_hG[k] * Wna[(48 + k) * HID + threadIdx.x];
        base_s[threadIdx.x] = b;
    }
    __syncthreads();

    int n = blockIdx.x * blockDim.x + threadIdx.x;
    if (n >= N_NODES) return;

    float acc[HID];
    #pragma unroll
    for (int j = 0; j < HID; j++) acc[j] = base_s[j];

    const float4* hr = reinterpret_cast<const float4*>(g_hi + (size_t)n * HID);
    #pragma unroll
    for (int k4 = 0; k4 < HID / 4; k4++) {
        float4 v = hr[k4];
        float vv[4] = {v.x, v.y, v.z, v.w};
        #pragma unroll
        for (int t = 0; t < 4; t++) {
            float hv = vv[t];
            int k = k4 * 4 + t;
            #pragma unroll
            for (int j = 0; j < HID; j++) acc[j] += hv * Wnas[k * HID + j];
        }
    }
    float inv_c = 1.f / fmaxf(g_rcnt[n], 1.f);
    const float4* mp = reinterpret_cast<const float4*>(g_mN + (size_t)n * EDGE_D);
    #pragma unroll
    for (int k4 = 0; k4 < EDGE_D / 4; k4++) {
        float4 v = mp[k4];
        float vv[4] = {v.x, v.y, v.z, v.w};
        #pragma unroll
        for (int t = 0; t < 4; t++) {
            float mv = vv[t] * inv_c;
            int k = 32 + k4 * 4 + t;
            #pragma unroll
            for (int j = 0; j < HID; j++) acc[j] += mv * Wnas[k * HID + j];
        }
    }
    #pragma unroll
    for (int j = 0; j < HID; j++) acc[j] = fmaxf(acc[j], 0.f);   // h_i2

    float q[OUT_C], s[OUT_C];
    #pragma unroll
    for (int j = 0; j < OUT_C; j++) { q[j] = 0.f; s[j] = 0.f; }
    #pragma unroll
    for (int k = 0; k < HID; k++) {
        float v = acc[k];
        #pragma unroll
        for (int j = 0; j < OUT_C; j++) {
            q[j] += v * Wls[k * OUT_C + j];
            s[j] += v * Wrs[k * OUT_C + j];
        }
    }
    float4* qo = reinterpret_cast<float4*>(g_q + (size_t)n * OUT_C);
    float4* so = reinterpret_cast<float4*>(g_s + (size_t)n * OUT_C);
    qo[0] = make_float4(q[0], q[1], q[2], q[3]);
    qo[1] = make_float4(q[4], q[5], q[6], q[7]);
    so[0] = make_float4(s[0], s[1], s[2], s[3]);
    so[1] = make_float4(s[4], s[5], s[6], s[7]);
}

// ---------------- kernel 5: edge pass 2 — 2 threads per edge ----------------
__global__ void __launch_bounds__(256)
k_edge2(const int* __restrict__ ei) {
    int t = blockIdx.x * blockDim.x + threadIdx.x;
    int e = t >> 1;
    if (e >= E_EDGES) return;
    int c = threadIdx.x & 1;
    int row = ei[e];
    int col = ei[E_EDGES + e];
    float4 q = *reinterpret_cast<const float4*>(g_q + (size_t)row * OUT_C + c * 4);
    red_add_f4(g_aggq + (size_t)col * OUT_C + c * 4, q.x, q.y, q.z, q.w);
    if (c == 0) atomicAdd(&g_ccnt[col], 1.f);
}

// ---------------- kernel 6: final node output + global mean pool ----------------
__global__ void __launch_bounds__(256)
k_node3(const float* __restrict__ bl) {
    __shared__ float pool_s[OUT_C];
    __shared__ float bls[OUT_C];
    if (threadIdx.x < OUT_C) { pool_s[threadIdx.x] = 0.f; bls[threadIdx.x] = bl[threadIdx.x]; }
    __syncthreads();

    int n = blockIdx.x * blockDim.x + threadIdx.x;
    float hn[OUT_C];
    #pragma unroll
    for (int j = 0; j < OUT_C; j++) hn[j] = 0.f;
    if (n < N_NODES) {
        float inv_c = 1.f / fmaxf(g_ccnt[n], 1.f);
        const float4* ap = reinterpret_cast<const float4*>(g_aggq + (size_t)n * OUT_C);
        const float4* sp = reinterpret_cast<const float4*>(g_s + (size_t)n * OUT_C);
        float4 a0 = ap[0], a1 = ap[1], s0 = sp[0], s1 = sp[1];
        hn[0] = a0.x * inv_c + bls[0] + s0.x;
        hn[1] = a0.y * inv_c + bls[1] + s0.y;
        hn[2] = a0.z * inv_c + bls[2] + s0.z;
        hn[3] = a0.w * inv_c + bls[3] + s0.w;
        hn[4] = a1.x * inv_c + bls[4] + s1.x;
        hn[5] = a1.y * inv_c + bls[5] + s1.y;
        hn[6] = a1.z * inv_c + bls[6] + s1.z;
        hn[7] = a1.w * inv_c + bls[7] + s1.w;
    }
    #pragma unroll
    for (int j = 0; j < OUT_C; j++) {
        float v = hn[j];
        #pragma unroll
        for (int off = 16; off > 0; off >>= 1)
            v += __shfl_down_sync(0xFFFFFFFFu, v, off);
        if ((threadIdx.x & 31) == 0) atomicAdd(&pool_s[j], v);
    }
    __syncthreads();
    if (threadIdx.x < OUT_C) atomicAdd(&g_pool[threadIdx.x], pool_s[threadIdx.x]);
}

// ---------------- kernel 7: pooled mean + log_softmax ----------------
__global__ void k_final(float* __restrict__ out) {
    if (threadIdx.x == 0) {
        float p[OUT_C];
        float mx = -1e30f;
        #pragma unroll
        for (int j = 0; j < OUT_C; j++) {
            p[j] = g_pool[j] / (float)N_NODES;
            mx = fmaxf(mx, p[j]);
        }
        float se = 0.f;
        #pragma unroll
        for (int j = 0; j < OUT_C; j++) se += expf(p[j] - mx);
        float lse = mx + logf(se);
        #pragma unroll
        for (int j = 0; j < OUT_C; j++) out[j] = p[j] - lse;
    }
}

// ---------------- launch ----------------
extern "C" void kernel_launch(void* const* d_in, const int* in_sizes, int n_in,
                              void* d_out, int out_size) {
    const float* x          = (const float*)d_in[0];
    const float* edge_attr  = (const float*)d_in[1];
    const float* graph_attr = (const float*)d_in[2];
    const int*   edge_index = (const int*)  d_in[3];
    // d_in[4] = batch (all zeros) — unused
    const float* W_node     = (const float*)d_in[5];
    const float* b_node     = (const float*)d_in[6];
    const float* W_graph    = (const float*)d_in[7];
    const float* b_graph    = (const float*)d_in[8];
    const float* W_edge_agg = (const float*)d_in[9];
    const float* b_edge_agg = (const float*)d_in[10];
    const float* W_node_agg = (const float*)d_in[11];
    const float* b_node_agg = (const float*)d_in[12];
    const float* W_sage_l   = (const float*)d_in[13];
    const float* b_sage_l   = (const float*)d_in[14];
    const float* W_sage_r   = (const float*)d_in[15];
    float* out = (float*)d_out;

    const int TB = 256;
    const int nodeBlocks  = (N_NODES + TB - 1) / TB;
    const int edge1Blocks = (E_EDGES * 4 + TB - 1) / TB;
    const int edge2Blocks = (E_EDGES * 2 + TB - 1) / TB;

    k_hG<<<1, 32>>>(graph_attr, W_graph, b_graph);
    k_nodeP<<<nodeBlocks, TB>>>(x, W_node, b_node, W_edge_agg, b_edge_agg);
    k_edge1<<<edge1Blocks, TB>>>(edge_index, edge_attr, W_edge_agg);
    k_node2<<<nodeBlocks, TB>>>(W_node_agg, b_node_agg, W_sage_l, W_sage_r);
    k_edge2<<<edge2Blocks, TB>>>(edge_index);
    k_node3<<<nodeBlocks, TB>>>(b_sage_l);
    k_final<<<1, 32>>>(out);
}